// round 15
// baseline (speedup 1.0000x reference)
#include <cuda_runtime.h>
#include <cuda_fp16.h>
#include <cstdint>

#define B_    16384
#define DIN_  1024
#define H_    512
#define DOUT_ 256
#define E_    8
#define NMID_ 2
#define EPS_  1e-5f

// ---------------- scratch (device globals: no allocs allowed) ----------------
__device__ float g_h[B_ * H_];
__device__ float g_y[B_ * H_];
__device__ float g_psum[1024][H_];      // per-CTA-tile column partial sums
__device__ float g_psq[1024][H_];
__device__ float g_p2sum[16][H_];       // stage-2 partials
__device__ float g_p2sq[16][H_];
__device__ float g_scale[H_];
__device__ float g_shift[H_];
__device__ int   g_act[B_];
__device__ int   g_cnt[E_];
__device__ int   g_off[E_];
__device__ int   g_pos[E_];
__device__ int   g_perm[B_];

__device__ __forceinline__ void mma_f16(float* c, const uint32_t* a, const uint32_t* b) {
    asm volatile(
        "mma.sync.aligned.m16n8k16.row.col.f32.f16.f16.f32 "
        "{%0,%1,%2,%3}, {%4,%5,%6,%7}, {%8,%9}, {%0,%1,%2,%3};"
        : "+f"(c[0]), "+f"(c[1]), "+f"(c[2]), "+f"(c[3])
        : "r"(a[0]), "r"(a[1]), "r"(a[2]), "r"(a[3]), "r"(b[0]), "r"(b[1]));
}
__device__ __forceinline__ void ldsm4(uint32_t* r, uint32_t saddr) {
    asm volatile("ldmatrix.sync.aligned.m8n8.x4.shared.b16 {%0,%1,%2,%3}, [%4];"
                 : "=r"(r[0]), "=r"(r[1]), "=r"(r[2]), "=r"(r[3]) : "r"(saddr));
}
__device__ __forceinline__ void ldsm4t(uint32_t* r, uint32_t saddr) {
    asm volatile("ldmatrix.sync.aligned.m8n8.x4.trans.shared.b16 {%0,%1,%2,%3}, [%4];"
                 : "=r"(r[0]), "=r"(r[1]), "=r"(r[2]), "=r"(r[3]) : "r"(saddr));
}
__device__ __forceinline__ uint32_t h2u(__half a, __half b) {
    const __half2 p = __halves2half2(a, b);
    return *(const uint32_t*)&p;
}

// SMEM per buffer: Ah[128x80B] Al[128x80B] Bh[32x272B] Bl[32x272B]
#define PADH_    40                     // A: fp16 units per row (80 B stride)
#define ROWB_    80
#define BROWB_   272                    // B: bytes per k-row (128 fp16 + 8 pad)
#define APART_B  (128 * ROWB_)          // 10240 B
#define BPART_B  (32 * BROWB_)          // 8704 B
#define BUFF_B   (2 * APART_B + 2 * BPART_B)   // 37888 B
#define SMEM_BYTES (2 * BUFF_B)                // 75776 B

// ============ 3xFP16-split mma.sync GEMM: C = relu(A @ W + bias) ============
// CTA tile 128x128, BK=32, 8 warps (2 m x 4 n), warp tile 64x32.
// A [*,KK] row-major (optional BN fuse + perm gather). W [KK,ldw] row-major.
// B stored [k][n] in smem, fragments via ldmatrix.trans.
// STATS: emit per-tile column sum/sumsq partials into g_psum/g_psq.
template<int KK, bool EXPERT, bool BN, bool STATS>
__global__ __launch_bounds__(256, 2) void mma_gemm(
    const float* __restrict__ A,
    const float* __restrict__ W, int ldw,
    const float* __restrict__ biasAll,
    const float* __restrict__ bnS, const float* __restrict__ bnB,
    float* __restrict__ C, int ldc)
{
    constexpr int NC = KK / 32;
    extern __shared__ __half smh[];

    const int tid  = threadIdx.x;
    const int wid  = tid >> 5;
    const int lane = tid & 31;
    const int gid  = lane >> 2;
    const int tig  = lane & 3;
    const int bm   = blockIdx.y * 128;
    const int bn0  = blockIdx.x * 128;
    const int slot = blockIdx.z * 128 + blockIdx.y;

    int cnt = B_, pbase = 0;
    const float* Wp   = W;
    const float* bias = biasAll;
    if (EXPERT) {
        const int e = blockIdx.z;
        cnt = g_cnt[e];
        if (bm >= cnt) {
            if (STATS) {
                for (int i = tid; i < 128; i += 256) {
                    g_psum[slot][bn0 + i] = 0.f;
                    g_psq[slot][bn0 + i]  = 0.f;
                }
            }
            return;
        }
        pbase = g_off[e];
        Wp    = W + (size_t)e * H_ * H_;
        bias  = biasAll + (size_t)e * H_;
    }

    // ---- fill assignments ----
    // A: thread -> (row = tid>>1, 16-float half = tid&1)
    const int arow = tid >> 1, ahalf = tid & 1;
    int grow = bm + arow;
    if (EXPERT) {
        const int lr = bm + arow;
        grow = g_perm[pbase + (lr < cnt ? lr : cnt - 1)];
    }
    const float* Arow = A + (size_t)grow * KK + ahalf * 16;
    // B: thread -> (k row bkk = tid>>3, 16 consecutive n at bnq)
    const int bkk = tid >> 3, bnq = (tid & 7) * 16;

    float4 a4[4];
    float4 b4[4];

    auto loadRegs = [&](int c) {
        const int k0 = c * 32;
        const float4* Ap = (const float4*)(Arow + k0);
#pragma unroll
        for (int j = 0; j < 4; j++) a4[j] = Ap[j];
        if (BN) {
            const float4* s4 = (const float4*)(bnS + k0 + ahalf * 16);
            const float4* t4 = (const float4*)(bnB + k0 + ahalf * 16);
#pragma unroll
            for (int j = 0; j < 4; j++) {
                float4 s = s4[j], t = t4[j];
                a4[j].x = fmaf(a4[j].x, s.x, t.x);
                a4[j].y = fmaf(a4[j].y, s.y, t.y);
                a4[j].z = fmaf(a4[j].z, s.z, t.z);
                a4[j].w = fmaf(a4[j].w, s.w, t.w);
            }
        }
        const float4* Wk = (const float4*)(Wp + (size_t)(k0 + bkk) * ldw + bn0 + bnq);
#pragma unroll
        for (int j = 0; j < 4; j++) b4[j] = Wk[j];
    };

    auto stash = [&](int buf) {
        char* base = (char*)smh + buf * BUFF_B;
        // A: 16 floats -> hi/lo, 2+2 STS.128
        {
            uint32_t hp[8], lp[8];
#pragma unroll
            for (int j = 0; j < 4; j++) {
                const float v[4] = { a4[j].x, a4[j].y, a4[j].z, a4[j].w };
                __half hi[4], lo[4];
#pragma unroll
                for (int q = 0; q < 4; q++) {
                    hi[q] = __float2half_rn(v[q]);
                    lo[q] = __float2half_rn(v[q] - __half2float(hi[q]));
                }
                hp[2 * j]     = h2u(hi[0], hi[1]);
                hp[2 * j + 1] = h2u(hi[2], hi[3]);
                lp[2 * j]     = h2u(lo[0], lo[1]);
                lp[2 * j + 1] = h2u(lo[2], lo[3]);
            }
            const int o = arow * ROWB_ + ahalf * 32;    // bytes
            uint4* dh = (uint4*)(base + o);
            uint4* dl = (uint4*)(base + APART_B + o);
            dh[0] = make_uint4(hp[0], hp[1], hp[2], hp[3]);
            dh[1] = make_uint4(hp[4], hp[5], hp[6], hp[7]);
            dl[0] = make_uint4(lp[0], lp[1], lp[2], lp[3]);
            dl[1] = make_uint4(lp[4], lp[5], lp[6], lp[7]);
        }
        // B: 16 floats (one k-row, 16 consecutive n) -> hi/lo, 2+2 STS.128
        {
            uint32_t hp[8], lp[8];
#pragma unroll
            for (int j = 0; j < 4; j++) {
                const float v[4] = { b4[j].x, b4[j].y, b4[j].z, b4[j].w };
                __half hi[4], lo[4];
#pragma unroll
                for (int q = 0; q < 4; q++) {
                    hi[q] = __float2half_rn(v[q]);
                    lo[q] = __float2half_rn(v[q] - __half2float(hi[q]));
                }
                hp[2 * j]     = h2u(hi[0], hi[1]);
                hp[2 * j + 1] = h2u(hi[2], hi[3]);
                lp[2 * j]     = h2u(lo[0], lo[1]);
                lp[2 * j + 1] = h2u(lo[2], lo[3]);
            }
            const int o = bkk * BROWB_ + bnq * 2;       // bytes
            uint4* dh = (uint4*)(base + 2 * APART_B + o);
            uint4* dl = (uint4*)(base + 2 * APART_B + BPART_B + o);
            dh[0] = make_uint4(hp[0], hp[1], hp[2], hp[3]);
            dh[1] = make_uint4(hp[4], hp[5], hp[6], hp[7]);
            dl[0] = make_uint4(lp[0], lp[1], lp[2], lp[3]);
            dl[1] = make_uint4(lp[4], lp[5], lp[6], lp[7]);
        }
    };

    // ---- accumulators ----
    float acc[4][4][4] = {};   // [mtile][ntile][frag]
    const int mbase = (wid & 1) * 64;
    const int nbase = (wid >> 1) * 32;

    const uint32_t sbase = (uint32_t)__cvta_generic_to_shared(smh);
    // A x4 lane address (unchanged layout)
    const uint32_t aLane = (uint32_t)((mbase + (lane & 15)) * ROWB_ + (lane >> 4) * 16);
    // B trans x4: tile m = lane>>3: k-half = m&1, n-half = m>>1; r = lane&7 is k-row
    const uint32_t bLane = (uint32_t)((((lane >> 3) & 1) * 8 + (lane & 7)) * BROWB_
                                      + ((lane >> 3) >> 1) * 16 + nbase * 2);

    auto domma = [&](int buf) {
        const uint32_t aH = sbase + buf * BUFF_B + aLane;
        const uint32_t aL = aH + APART_B;
        const uint32_t bH = sbase + buf * BUFF_B + 2 * APART_B + bLane;
        const uint32_t bL = bH + BPART_B;
#pragma unroll
        for (int ks = 0; ks < 2; ks++) {
            uint32_t bh[2][4], bl[2][4];   // [ntp][b0 even, b1 even, b0 odd, b1 odd]
#pragma unroll
            for (int ntp = 0; ntp < 2; ntp++) {
                const uint32_t off = (uint32_t)(ks * 16 * BROWB_ + ntp * 32);
                ldsm4t(bh[ntp], bH + off);
                ldsm4t(bl[ntp], bL + off);
            }
#pragma unroll
            for (int mt = 0; mt < 4; mt++) {
                uint32_t ah[4], al[4];
                const uint32_t off = (uint32_t)(mt * 16 * ROWB_ + ks * 32);
                ldsm4(ah, aH + off);
                ldsm4(al, aL + off);
#pragma unroll
                for (int nt = 0; nt < 4; nt++) {
                    const uint32_t* bhp = &bh[nt >> 1][(nt & 1) * 2];
                    const uint32_t* blp = &bl[nt >> 1][(nt & 1) * 2];
                    mma_f16(acc[mt][nt], ah, bhp);
                    mma_f16(acc[mt][nt], ah, blp);
                    mma_f16(acc[mt][nt], al, bhp);
                }
            }
        }
    };

    // ---- pipeline ----
    loadRegs(0);
    stash(0);
    __syncthreads();
    int buf = 0;
    for (int c = 0; c < NC; c++) {
        const bool more = (c + 1 < NC);
        if (more) loadRegs(c + 1);
        domma(buf);
        if (more) stash(buf ^ 1);
        __syncthreads();
        buf ^= 1;
    }

    // ---- epilogue: bias + relu (+ fused column stats) ----
    float cs[4][2], cq[4][2];
    if (STATS) {
#pragma unroll
        for (int nt = 0; nt < 4; nt++) {
            cs[nt][0] = cs[nt][1] = 0.f;
            cq[nt][0] = cq[nt][1] = 0.f;
        }
    }
#pragma unroll
    for (int mt = 0; mt < 4; mt++) {
#pragma unroll
        for (int half = 0; half < 2; half++) {
            const int lrow = mbase + mt * 16 + gid + half * 8;   // tile-local 0..127
            bool valid = true;
            int orow = bm + lrow;
            if (EXPERT) {
                valid = (bm + lrow) < cnt;
                orow  = valid ? g_perm[pbase + bm + lrow] : 0;
            }
            if (!valid) continue;
            float* Cr = C + (size_t)orow * ldc + bn0;
#pragma unroll
            for (int nt = 0; nt < 4; nt++) {
                const int n = nbase + nt * 8 + tig * 2;
                const float2 bv = *(const float2*)(bias + bn0 + n);
                float2 o;
                o.x = fmaxf(acc[mt][nt][half * 2 + 0] + bv.x, 0.f);
                o.y = fmaxf(acc[mt][nt][half * 2 + 1] + bv.y, 0.f);
                *(float2*)(Cr + n) = o;
                if (STATS) {
                    cs[nt][0] += o.x; cq[nt][0] += o.x * o.x;
                    cs[nt][1] += o.y; cq[nt][1] += o.y * o.y;
                }
            }
        }
    }

    if (STATS) {
        __shared__ float s_cs[128], s_cq[128];
        __syncthreads();
        for (int i = tid; i < 128; i += 256) { s_cs[i] = 0.f; s_cq[i] = 0.f; }
        __syncthreads();
#pragma unroll
        for (int nt = 0; nt < 4; nt++) {
#pragma unroll
            for (int cc = 0; cc < 2; cc++) {
                float v = cs[nt][cc], w = cq[nt][cc];
#pragma unroll
                for (int mk = 4; mk <= 16; mk <<= 1) {
                    v += __shfl_xor_sync(0xffffffffu, v, mk);
                    w += __shfl_xor_sync(0xffffffffu, w, mk);
                }
                if (gid == 0) {
                    const int col = nbase + nt * 8 + tig * 2 + cc;
                    atomicAdd(&s_cs[col], v);    // exactly 2 adds/col: deterministic
                    atomicAdd(&s_cq[col], w);
                }
            }
        }
        __syncthreads();
        for (int i = tid; i < 128; i += 256) {
            g_psum[slot][bn0 + i] = s_cs[i];
            g_psq[slot][bn0 + i]  = s_cq[i];
        }
    }
}

// ---------------- stage-2 partial reduction: npart slots -> 16 ---------------
__global__ void bn_reduce(int npart)
{
    __shared__ float ss[8][33], sq[8][33];
    const int tx = threadIdx.x, ty = threadIdx.y;
    const int col = blockIdx.x * 32 + tx;
    const int per = npart >> 4;
    const int base = blockIdx.y * per;
    float s = 0.f, q = 0.f;
    for (int p = ty; p < per; p += 8) {
        s += g_psum[base + p][col];
        q += g_psq[base + p][col];
    }
    ss[ty][tx] = s; sq[ty][tx] = q;
    __syncthreads();
    if (ty == 0) {
#pragma unroll
        for (int y = 1; y < 8; y++) { s += ss[y][tx]; q += sq[y][tx]; }
        g_p2sum[blockIdx.y][col] = s;
        g_p2sq[blockIdx.y][col]  = q;
    }
}

__global__ void mlnn_bn_finalize(const float* __restrict__ gamma,
                                 const float* __restrict__ beta)
{
    const int c = blockIdx.x * 256 + threadIdx.x;
    float s = 0.f, q = 0.f;
#pragma unroll
    for (int p = 0; p < 16; p++) { s += g_p2sum[p][c]; q += g_p2sq[p][c]; }
    const float m   = s * (1.f / B_);
    const float var = q * (1.f / B_) - m * m;
    const float sc  = gamma[c] / sqrtf(var + EPS_);
    g_scale[c] = sc;
    g_shift[c] = beta[c] - m * sc;
    if (blockIdx.x == 0 && threadIdx.x < E_) g_cnt[threadIdx.x] = 0;
}

// ---------------- routing: warp per row, float4, BN fused --------------------
__global__ __launch_bounds__(256)
void mlnn_routing(const float* __restrict__ h,
                  const float* __restrict__ W,    // [H,E]
                  const float* __restrict__ b)    // [E]
{
    __shared__ float Wt[E_ * H_];
    const int tid = threadIdx.x;
    for (int i = tid; i < H_ * E_; i += 256) {
        const int k = i >> 3, e = i & 7;
        Wt[e * H_ + k] = W[i];
    }
    __syncthreads();
    const int warp = tid >> 5, lane = tid & 31;
    const int row  = blockIdx.x * 8 + warp;
    const float4* hr = (const float4*)(h + (size_t)row * H_);
    float acc[E_] = {};
#pragma unroll
    for (int i = 0; i < H_ / 128; i++) {
        const int k4 = i * 32 + lane;
        const int k  = k4 * 4;
        const float4 v = hr[k4];
        const float4 s = *(const float4*)(g_scale + k);
        const float4 t = *(const float4*)(g_shift + k);
        const float h0 = fmaf(v.x, s.x, t.x);
        const float h1 = fmaf(v.y, s.y, t.y);
        const float h2 = fmaf(v.z, s.z, t.z);
        const float h3 = fmaf(v.w, s.w, t.w);
#pragma unroll
        for (int e = 0; e < E_; e++) {
            const float4 w = *(const float4*)&Wt[e * H_ + k];
            acc[e] += h0 * w.x + h1 * w.y + h2 * w.z + h3 * w.w;
        }
    }
#pragma unroll
    for (int e = 0; e < E_; e++)
#pragma unroll
        for (int off = 16; off; off >>= 1)
            acc[e] += __shfl_xor_sync(0xffffffffu, acc[e], off);
    if (lane == 0) {
        float best = acc[0] + b[0];
        int bi = 0;
#pragma unroll
        for (int e = 1; e < E_; e++) {
            const float v = acc[e] + b[e];
            if (v > best) { best = v; bi = e; }
        }
        g_act[row] = bi;
        atomicAdd(&g_cnt[bi], 1);
    }
}

__global__ void mlnn_scan()
{
    if (threadIdx.x == 0) {
        int s = 0;
#pragma unroll
        for (int e = 0; e < E_; e++) { g_off[e] = s; g_pos[e] = s; s += g_cnt[e]; }
    }
}

__global__ void mlnn_scatter()
{
    const int r = blockIdx.x * 256 + threadIdx.x;
    const int a = g_act[r];
    const int p = atomicAdd(&g_pos[a], 1);
    g_perm[p] = r;
}

// ---------------- launch ----------------
extern "C" void kernel_launch(void* const* d_in, const int* in_sizes, int n_in,
                              void* d_out, int out_size)
{
    const float* x     = (const float*)d_in[0];
    const float* dqn_W = (const float*)d_in[1];
    const float* dqn_b = (const float*)d_in[2];
    const float* Ws    = (const float*)d_in[3];
    const float* bs    = (const float*)d_in[4];
    const float* g0    = (const float*)d_in[5];
    const float* b0    = (const float*)d_in[6];
    const float* We    = (const float*)d_in[7];
    const float* be    = (const float*)d_in[8];
    const float* gmid  = (const float*)d_in[9];
    const float* bmid  = (const float*)d_in[10];
    const float* Wend  = (const float*)d_in[11];
    const float* bend  = (const float*)d_in[12];
    float* out = (float*)d_out;

    float *h, *y, *scl, *shf;
    cudaGetSymbolAddress((void**)&h,   g_h);
    cudaGetSymbolAddress((void**)&y,   g_y);
    cudaGetSymbolAddress((void**)&scl, g_scale);
    cudaGetSymbolAddress((void**)&shf, g_shift);

    cudaFuncSetAttribute(mma_gemm<1024, false, false, true>,
                         cudaFuncAttributeMaxDynamicSharedMemorySize, SMEM_BYTES);
    cudaFuncSetAttribute(mma_gemm<512, true, true, true>,
                         cudaFuncAttributeMaxDynamicSharedMemorySize, SMEM_BYTES);
    cudaFuncSetAttribute(mma_gemm<512, false, true, false>,
                         cudaFuncAttributeMaxDynamicSharedMemorySize, SMEM_BYTES);

    // ---- start layer: h = relu(x @ Ws + bs); fused stats -> finalize ----
    mma_gemm<1024, false, false, true><<<dim3(H_ / 128, B_ / 128), 256, SMEM_BYTES>>>(
        x, Ws, H_, bs, nullptr, nullptr, h, H_);
    bn_reduce<<<dim3(H_ / 32, 16), dim3(32, 8)>>>(128);
    mlnn_bn_finalize<<<2, 256>>>(g0, b0);

    float* cur = h;
    float* nxt = y;
    for (int l = 0; l < NMID_; l++) {
        mlnn_routing<<<B_ / 8, 256>>>(cur, dqn_W, dqn_b);
        mlnn_scan<<<1, 1>>>();
        mlnn_scatter<<<B_ / 256, 256>>>();
        mma_gemm<512, true, true, true><<<dim3(H_ / 128, B_ / 128, E_), 256, SMEM_BYTES>>>(
            cur, We + (size_t)l * E_ * H_ * H_, H_,
            be + (size_t)l * E_ * H_, scl, shf, nxt, H_);
        bn_reduce<<<dim3(H_ / 32, 16), dim3(32, 8)>>>(1024);
        mlnn_bn_finalize<<<2, 256>>>(gmid + (size_t)l * H_, bmid + (size_t)l * H_);
        float* t = cur; cur = nxt; nxt = t;
    }

    // ---- end layer: out = relu(h @ Wend + bend), BN of last layer fused ----
    mma_gemm<512, false, true, false><<<dim3(DOUT_ / 128, B_ / 128), 256, SMEM_BYTES>>>(
        cur, Wend, DOUT_, bend, scl, shf, out, DOUT_);
}

// round 16
// speedup vs baseline: 1.0255x; 1.0255x over previous
#include <cuda_runtime.h>
#include <cuda_fp16.h>
#include <cstdint>

#define B_    16384
#define DIN_  1024
#define H_    512
#define DOUT_ 256
#define E_    8
#define NMID_ 2
#define EPS_  1e-5f

// ---------------- scratch (device globals: no allocs allowed) ----------------
__device__ float g_h[B_ * H_];
__device__ float g_y[B_ * H_];
__device__ float g_psum[1024][H_];      // per-CTA-tile column partial sums
__device__ float g_psq[1024][H_];
__device__ float g_p2sum[16][H_];       // stage-2 partials
__device__ float g_p2sq[16][H_];
__device__ float g_scale[H_];
__device__ float g_shift[H_];
__device__ __align__(16) float g_rw[H_ * E_];   // routing weights, BN-folded, [k][e]
__device__ float g_rc[E_];                      // routing const: t@W + b
__device__ int   g_act[B_];
__device__ int   g_cnt[E_];
__device__ int   g_off[E_];
__device__ int   g_pos[E_];
__device__ int   g_perm[B_];

__device__ __forceinline__ void mma_f16(float* c, const uint32_t* a, const uint32_t* b) {
    asm volatile(
        "mma.sync.aligned.m16n8k16.row.col.f32.f16.f16.f32 "
        "{%0,%1,%2,%3}, {%4,%5,%6,%7}, {%8,%9}, {%0,%1,%2,%3};"
        : "+f"(c[0]), "+f"(c[1]), "+f"(c[2]), "+f"(c[3])
        : "r"(a[0]), "r"(a[1]), "r"(a[2]), "r"(a[3]), "r"(b[0]), "r"(b[1]));
}
__device__ __forceinline__ void ldsm4(uint32_t* r, uint32_t saddr) {
    asm volatile("ldmatrix.sync.aligned.m8n8.x4.shared.b16 {%0,%1,%2,%3}, [%4];"
                 : "=r"(r[0]), "=r"(r[1]), "=r"(r[2]), "=r"(r[3]) : "r"(saddr));
}

// SMEM (fp16): per buffer: Ah[128*40] Al[128*40] Bh[128*40] Bl[128*40]
#define PADH_    40                     // fp16 units per row (80 B stride)
#define ROWB_    (PADH_ * 2)            // 80 bytes
#define PART_B   (128 * ROWB_)          // 10240 B per part
#define BUFF_B   (4 * PART_B)           // 40960 B per buffer
#define SMEM_BYTES (2 * BUFF_B)         // 81920 B

// ============ 3xFP16-split mma.sync GEMM: C = relu(A @ W + bias) ============
// CTA tile 128x128, BK=32, 8 warps (2 m-groups x 4 n-groups), warp tile 64x32.
// A [*,KK] row-major (optional BN fuse + perm gather). W [KK,ldw] row-major.
// STATS: emit per-tile column sum/sumsq partials into g_psum/g_psq.
template<int KK, bool EXPERT, bool BN, bool STATS>
__global__ __launch_bounds__(256, 2) void mma_gemm(
    const float* __restrict__ A,
    const float* __restrict__ W, int ldw,
    const float* __restrict__ biasAll,
    const float* __restrict__ bnS, const float* __restrict__ bnB,
    float* __restrict__ C, int ldc)
{
    constexpr int NC = KK / 32;
    extern __shared__ __half smh[];

    const int tid  = threadIdx.x;
    const int wid  = tid >> 5;
    const int lane = tid & 31;
    const int gid  = lane >> 2;
    const int tig  = lane & 3;
    const int bm   = blockIdx.y * 128;
    const int bn0  = blockIdx.x * 128;
    const int slot = blockIdx.z * 128 + blockIdx.y;

    int cnt = B_, pbase = 0;
    const float* Wp   = W;
    const float* bias = biasAll;
    if (EXPERT) {
        const int e = blockIdx.z;
        cnt = g_cnt[e];
        if (bm >= cnt) {
            if (STATS) {
                for (int i = tid; i < 128; i += 256) {
                    g_psum[slot][bn0 + i] = 0.f;
                    g_psq[slot][bn0 + i]  = 0.f;
                }
            }
            return;
        }
        pbase = g_off[e];
        Wp    = W + (size_t)e * H_ * H_;
        bias  = biasAll + (size_t)e * H_;
    }

    // ---- fill assignments ----
    const int arow = tid >> 1, ahalf = tid & 1;
    int grow = bm + arow;
    if (EXPERT) {
        const int lr = bm + arow;
        grow = g_perm[pbase + (lr < cnt ? lr : cnt - 1)];
    }
    const float* Arow = A + (size_t)grow * KK + ahalf * 16;
    const int bkk = tid >> 3, bnl = tid & 7;

    float4 a4[4];
    float  bb[16];

    auto loadRegs = [&](int c) {
        const int k0 = c * 32;
        const float4* Ap = (const float4*)(Arow + k0);
#pragma unroll
        for (int j = 0; j < 4; j++) a4[j] = Ap[j];
        if (BN) {
            const float4* s4 = (const float4*)(bnS + k0 + ahalf * 16);
            const float4* t4 = (const float4*)(bnB + k0 + ahalf * 16);
#pragma unroll
            for (int j = 0; j < 4; j++) {
                float4 s = s4[j], t = t4[j];
                a4[j].x = fmaf(a4[j].x, s.x, t.x);
                a4[j].y = fmaf(a4[j].y, s.y, t.y);
                a4[j].z = fmaf(a4[j].z, s.z, t.z);
                a4[j].w = fmaf(a4[j].w, s.w, t.w);
            }
        }
        const float* Wk = Wp + (size_t)(k0 + bkk) * ldw + bn0 + bnl;
#pragma unroll
        for (int j = 0; j < 16; j++) bb[j] = __ldg(Wk + 8 * j);
    };

    auto stash = [&](int buf) {
        __half* Ah = smh + buf * (BUFF_B / 2);
        __half* Al = Ah + PART_B / 2;
        __half* Bh = Al + PART_B / 2;
        __half* Bl = Bh + PART_B / 2;
#pragma unroll
        for (int j = 0; j < 4; j++) {
            const float v[4] = { a4[j].x, a4[j].y, a4[j].z, a4[j].w };
            __half hi[4], lo[4];
#pragma unroll
            for (int q = 0; q < 4; q++) {
                hi[q] = __float2half_rn(v[q]);
                lo[q] = __float2half_rn(v[q] - __half2float(hi[q]));
            }
            const int o = arow * PADH_ + ahalf * 16 + j * 4;   // fp16 units, 8B aligned
            *(__half2*)(Ah + o)     = __halves2half2(hi[0], hi[1]);
            *(__half2*)(Ah + o + 2) = __halves2half2(hi[2], hi[3]);
            *(__half2*)(Al + o)     = __halves2half2(lo[0], lo[1]);
            *(__half2*)(Al + o + 2) = __halves2half2(lo[2], lo[3]);
        }
#pragma unroll
        for (int j = 0; j < 16; j++) {
            const int n = bnl + 8 * j;
            const __half hi = __float2half_rn(bb[j]);
            Bh[n * PADH_ + bkk] = hi;
            Bl[n * PADH_ + bkk] = __float2half_rn(bb[j] - __half2float(hi));
        }
    };

    // ---- accumulators ----
    float acc[4][4][4] = {};   // [mtile][ntile][frag]
    const int mbase = (wid & 1) * 64;
    const int nbase = (wid >> 1) * 32;

    const uint32_t sbase = (uint32_t)__cvta_generic_to_shared(smh);
    const uint32_t aLane = (uint32_t)((mbase + (lane & 15)) * ROWB_ + (lane >> 4) * 16);
    const uint32_t bLane = (uint32_t)((nbase + (((lane >> 3) >> 1) * 8) + (lane & 7)) * ROWB_
                                      + ((lane >> 3) & 1) * 16);

    auto domma = [&](int buf) {
        const uint32_t aH = sbase + buf * BUFF_B + aLane;
        const uint32_t aL = aH + PART_B;
        const uint32_t bH = sbase + buf * BUFF_B + 2 * PART_B + bLane;
        const uint32_t bL = bH + PART_B;
#pragma unroll
        for (int ks = 0; ks < 2; ks++) {
            uint32_t bh[2][4], bl[2][4];
#pragma unroll
            for (int ntp = 0; ntp < 2; ntp++) {
                const uint32_t off = (uint32_t)(ntp * 16 * ROWB_ + ks * 32);
                ldsm4(bh[ntp], bH + off);
                ldsm4(bl[ntp], bL + off);
            }
#pragma unroll
            for (int mt = 0; mt < 4; mt++) {
                uint32_t ah[4], al[4];
                const uint32_t off = (uint32_t)(mt * 16 * ROWB_ + ks * 32);
                ldsm4(ah, aH + off);
                ldsm4(al, aL + off);
#pragma unroll
                for (int nt = 0; nt < 4; nt++) {
                    const uint32_t* bhp = &bh[nt >> 1][(nt & 1) * 2];
                    const uint32_t* blp = &bl[nt >> 1][(nt & 1) * 2];
                    mma_f16(acc[mt][nt], ah, bhp);
                    mma_f16(acc[mt][nt], ah, blp);
                    mma_f16(acc[mt][nt], al, bhp);
                }
            }
        }
    };

    // ---- pipeline ----
    loadRegs(0);
    stash(0);
    __syncthreads();
    int buf = 0;
    for (int c = 0; c < NC; c++) {
        const bool more = (c + 1 < NC);
        if (more) loadRegs(c + 1);
        domma(buf);
        if (more) stash(buf ^ 1);
        __syncthreads();
        buf ^= 1;
    }

    // ---- epilogue: bias + relu (+ fused column stats) ----
    float cs[4][2], cq[4][2];
    if (STATS) {
#pragma unroll
        for (int nt = 0; nt < 4; nt++) {
            cs[nt][0] = cs[nt][1] = 0.f;
            cq[nt][0] = cq[nt][1] = 0.f;
        }
    }
#pragma unroll
    for (int mt = 0; mt < 4; mt++) {
#pragma unroll
        for (int half = 0; half < 2; half++) {
            const int lrow = mbase + mt * 16 + gid + half * 8;   // tile-local 0..127
            bool valid = true;
            int orow = bm + lrow;
            if (EXPERT) {
                valid = (bm + lrow) < cnt;
                orow  = valid ? g_perm[pbase + bm + lrow] : 0;
            }
            if (!valid) continue;
            float* Cr = C + (size_t)orow * ldc + bn0;
#pragma unroll
            for (int nt = 0; nt < 4; nt++) {
                const int n = nbase + nt * 8 + tig * 2;
                const float2 bv = *(const float2*)(bias + bn0 + n);
                float2 o;
                o.x = fmaxf(acc[mt][nt][half * 2 + 0] + bv.x, 0.f);
                o.y = fmaxf(acc[mt][nt][half * 2 + 1] + bv.y, 0.f);
                *(float2*)(Cr + n) = o;
                if (STATS) {
                    cs[nt][0] += o.x; cq[nt][0] += o.x * o.x;
                    cs[nt][1] += o.y; cq[nt][1] += o.y * o.y;
                }
            }
        }
    }

    if (STATS) {
        __shared__ float s_cs[128], s_cq[128];
        __syncthreads();
        for (int i = tid; i < 128; i += 256) { s_cs[i] = 0.f; s_cq[i] = 0.f; }
        __syncthreads();
#pragma unroll
        for (int nt = 0; nt < 4; nt++) {
#pragma unroll
            for (int cc = 0; cc < 2; cc++) {
                float v = cs[nt][cc], w = cq[nt][cc];
#pragma unroll
                for (int mk = 4; mk <= 16; mk <<= 1) {
                    v += __shfl_xor_sync(0xffffffffu, v, mk);
                    w += __shfl_xor_sync(0xffffffffu, w, mk);
                }
                if (gid == 0) {
                    const int col = nbase + nt * 8 + tig * 2 + cc;
                    atomicAdd(&s_cs[col], v);    // exactly 2 adds/col: deterministic
                    atomicAdd(&s_cq[col], w);
                }
            }
        }
        __syncthreads();
        for (int i = tid; i < 128; i += 256) {
            g_psum[slot][bn0 + i] = s_cs[i];
            g_psq[slot][bn0 + i]  = s_cq[i];
        }
    }
}

// ---------------- stage-2 partial reduction: npart slots -> 16 ---------------
__global__ void bn_reduce(int npart)
{
    __shared__ float ss[8][33], sq[8][33];
    const int tx = threadIdx.x, ty = threadIdx.y;
    const int col = blockIdx.x * 32 + tx;
    const int per = npart >> 4;
    const int base = blockIdx.y * per;
    float s = 0.f, q = 0.f;
    for (int p = ty; p < per; p += 8) {
        s += g_psum[base + p][col];
        q += g_psq[base + p][col];
    }
    ss[ty][tx] = s; sq[ty][tx] = q;
    __syncthreads();
    if (ty == 0) {
#pragma unroll
        for (int y = 1; y < 8; y++) { s += ss[y][tx]; q += sq[y][tx]; }
        g_p2sum[blockIdx.y][col] = s;
        g_p2sq[blockIdx.y][col]  = q;
    }
}

__global__ void mlnn_bn_finalize(const float* __restrict__ gamma,
                                 const float* __restrict__ beta)
{
    const int c = blockIdx.x * 256 + threadIdx.x;
    float s = 0.f, q = 0.f;
#pragma unroll
    for (int p = 0; p < 16; p++) { s += g_p2sum[p][c]; q += g_p2sq[p][c]; }
    const float m   = s * (1.f / B_);
    const float var = q * (1.f / B_) - m * m;
    const float sc  = gamma[c] / sqrtf(var + EPS_);
    g_scale[c] = sc;
    g_shift[c] = beta[c] - m * sc;
    if (blockIdx.x == 0 && threadIdx.x < E_) g_cnt[threadIdx.x] = 0;
}

// -------- prep_route: rw[k][e] = s_k*W[k][e]; rc[e] = sum_k t_k*W[k][e] + b[e]
__global__ void prep_route(const float* __restrict__ W,   // [H, E]
                           const float* __restrict__ b)   // [E]
{
    const int tid  = threadIdx.x;
    const int lane = tid & 31, warp = tid >> 5;
    float tacc[E_] = {};
    for (int c = tid; c < H_; c += 256) {
        const float s = g_scale[c], t = g_shift[c];
        const float4 w0 = *(const float4*)(W + c * E_);
        const float4 w1 = *(const float4*)(W + c * E_ + 4);
        float4 o0, o1;
        o0.x = s * w0.x; o0.y = s * w0.y; o0.z = s * w0.z; o0.w = s * w0.w;
        o1.x = s * w1.x; o1.y = s * w1.y; o1.z = s * w1.z; o1.w = s * w1.w;
        *(float4*)(g_rw + c * E_)     = o0;
        *(float4*)(g_rw + c * E_ + 4) = o1;
        tacc[0] += t * w0.x; tacc[1] += t * w0.y;
        tacc[2] += t * w0.z; tacc[3] += t * w0.w;
        tacc[4] += t * w1.x; tacc[5] += t * w1.y;
        tacc[6] += t * w1.z; tacc[7] += t * w1.w;
    }
    __shared__ float red[8][E_];
#pragma unroll
    for (int e = 0; e < E_; e++)
#pragma unroll
        for (int off = 16; off; off >>= 1)
            tacc[e] += __shfl_xor_sync(0xffffffffu, tacc[e], off);
    if (lane == 0)
#pragma unroll
        for (int e = 0; e < E_; e++) red[warp][e] = tacc[e];
    __syncthreads();
    if (tid < E_) {
        float s = 0.f;
#pragma unroll
        for (int w = 0; w < 8; w++) s += red[w][tid];
        g_rc[tid] = s + b[tid];
    }
}

// ---------------- routing: 4 rows/warp, swizzled smem weights ----------------
#define SWZ_(o) ((o) ^ (((o) >> 3) & 0x70))

__global__ __launch_bounds__(256)
void mlnn_routing(const float* __restrict__ h)
{
    __shared__ __align__(16) char Wt[H_ * E_ * 4];   // 16 KB, swizzled
    __shared__ float rc[E_];
    const int tid = threadIdx.x;
    {
        const float4* src = (const float4*)g_rw;
        for (int i = tid; i < H_ * E_ / 4; i += 256) {
            const uint32_t o = (uint32_t)(i * 16);
            *(float4*)(Wt + SWZ_(o)) = src[i];
        }
        if (tid < E_) rc[tid] = g_rc[tid];
    }
    __syncthreads();
    const int warp = tid >> 5, lane = tid & 31;
    const int row0 = blockIdx.x * 32 + warp * 4;
    const float4* r0 = (const float4*)(h + (size_t)(row0 + 0) * H_);
    const float4* r1 = (const float4*)(h + (size_t)(row0 + 1) * H_);
    const float4* r2 = (const float4*)(h + (size_t)(row0 + 2) * H_);
    const float4* r3 = (const float4*)(h + (size_t)(row0 + 3) * H_);

    float acc[4][E_];
#pragma unroll
    for (int r = 0; r < 4; r++)
#pragma unroll
        for (int e = 0; e < E_; e++) acc[r][e] = 0.f;

#pragma unroll
    for (int i = 0; i < H_ / 128; i++) {
        const int k4 = i * 32 + lane;                // lane owns k = 4*k4 .. 4*k4+3
        float va[4][4];
        *(float4*)va[0] = r0[k4];
        *(float4*)va[1] = r1[k4];
        *(float4*)va[2] = r2[k4];
        *(float4*)va[3] = r3[k4];
        const uint32_t ob = (uint32_t)(i * 4096 + lane * 128);
#pragma unroll
        for (int j = 0; j < 4; j++) {
            float w[8];
            const uint32_t o = ob + j * 32;
            *(float4*)(w)     = *(const float4*)(Wt + SWZ_(o));
            *(float4*)(w + 4) = *(const float4*)(Wt + SWZ_(o + 16));
#pragma unroll
            for (int e = 0; e < E_; e++) {
#pragma unroll
                for (int r = 0; r < 4; r++)
                    acc[r][e] = fmaf(va[r][j], w[e], acc[r][e]);
            }
        }
    }

#pragma unroll
    for (int r = 0; r < 4; r++)
#pragma unroll
        for (int e = 0; e < E_; e++)
#pragma unroll
            for (int off = 16; off; off >>= 1)
                acc[r][e] += __shfl_xor_sync(0xffffffffu, acc[r][e], off);

    if (lane == 0) {
#pragma unroll
        for (int r = 0; r < 4; r++) {
            float best = acc[r][0] + rc[0];
            int bi = 0;
#pragma unroll
            for (int e = 1; e < E_; e++) {
                const float v = acc[r][e] + rc[e];
                if (v > best) { best = v; bi = e; }   // strict > == jnp first-max
            }
            g_act[row0 + r] = bi;
            atomicAdd(&g_cnt[bi], 1);
        }
    }
}

__global__ void mlnn_scan()
{
    if (threadIdx.x == 0) {
        int s = 0;
#pragma unroll
        for (int e = 0; e < E_; e++) { g_off[e] = s; g_pos[e] = s; s += g_cnt[e]; }
    }
}

__global__ void mlnn_scatter()
{
    const int r = blockIdx.x * 256 + threadIdx.x;
    const int a = g_act[r];
    const int p = atomicAdd(&g_pos[a], 1);
    g_perm[p] = r;
}

// ---------------- launch ----------------
extern "C" void kernel_launch(void* const* d_in, const int* in_sizes, int n_in,
                              void* d_out, int out_size)
{
    const float* x     = (const float*)d_in[0];
    const float* dqn_W = (const float*)d_in[1];
    const float* dqn_b = (const float*)d_in[2];
    const float* Ws    = (const float*)d_in[3];
    const float* bs    = (const float*)d_in[4];
    const float* g0    = (const float*)d_in[5];
    const float* b0    = (const float*)d_in[6];
    const float* We    = (const float*)d_in[7];
    const float* be    = (const float*)d_in[8];
    const float* gmid  = (const float*)d_in[9];
    const float* bmid  = (const float*)d_in[10];
    const float* Wend  = (const float*)d_in[11];
    const float* bend  = (const float*)d_in[12];
    float* out = (float*)d_out;

    float *h, *y, *scl, *shf;
    cudaGetSymbolAddress((void**)&h,   g_h);
    cudaGetSymbolAddress((void**)&y,   g_y);
    cudaGetSymbolAddress((void**)&scl, g_scale);
    cudaGetSymbolAddress((void**)&shf, g_shift);

    cudaFuncSetAttribute(mma_gemm<1024, false, false, true>,
                         cudaFuncAttributeMaxDynamicSharedMemorySize, SMEM_BYTES);
    cudaFuncSetAttribute(mma_gemm<512, true, true, true>,
                         cudaFuncAttributeMaxDynamicSharedMemorySize, SMEM_BYTES);
    cudaFuncSetAttribute(mma_gemm<512, false, true, false>,
                         cudaFuncAttributeMaxDynamicSharedMemorySize, SMEM_BYTES);

    // ---- start layer: h = relu(x @ Ws + bs); fused stats -> finalize ----
    mma_gemm<1024, false, false, true><<<dim3(H_ / 128, B_ / 128), 256, SMEM_BYTES>>>(
        x, Ws, H_, bs, nullptr, nullptr, h, H_);
    bn_reduce<<<dim3(H_ / 32, 16), dim3(32, 8)>>>(128);
    mlnn_bn_finalize<<<2, 256>>>(g0, b0);

    float* cur = h;
    float* nxt = y;
    for (int l = 0; l < NMID_; l++) {
        prep_route<<<1, 256>>>(dqn_W, dqn_b);
        mlnn_routing<<<B_ / 32, 256>>>(cur);
        mlnn_scan<<<1, 1>>>();
        mlnn_scatter<<<B_ / 256, 256>>>();
        mma_gemm<512, true, true, true><<<dim3(H_ / 128, B_ / 128, E_), 256, SMEM_BYTES>>>(
            cur, We + (size_t)l * E_ * H_ * H_, H_,
            be + (size_t)l * E_ * H_, scl, shf, nxt, H_);
        bn_reduce<<<dim3(H_ / 32, 16), dim3(32, 8)>>>(1024);
        mlnn_bn_finalize<<<2, 256>>>(gmid + (size_t)l * H_, bmid + (size_t)l * H_);
        float* t = cur; cur = nxt; nxt = t;
    }

    // ---- end layer: out = relu(h @ Wend + bend), BN of last layer fused ----
    mma_gemm<512, false, true, false><<<dim3(DOUT_ / 128, B_ / 128), 256, SMEM_BYTES>>>(
        cur, Wend, DOUT_, bend, scl, shf, out, DOUT_);
}

// round 17
// speedup vs baseline: 1.1190x; 1.0912x over previous
#include <cuda_runtime.h>
#include <cuda_fp16.h>
#include <cstdint>

#define B_    16384
#define DIN_  1024
#define H_    512
#define DOUT_ 256
#define E_    8
#define NMID_ 2
#define EPS_  1e-5f

// ---------------- scratch (device globals: no allocs allowed) ----------------
__device__ __half g_xh[B_ * DIN_];      // pre-split input x
__device__ __half g_xl[B_ * DIN_];
__device__ __half g_ah[B_ * H_];        // activation ping (hi/lo)
__device__ __half g_al[B_ * H_];
__device__ __half g_bh[B_ * H_];        // activation pong
__device__ __half g_bl[B_ * H_];
__device__ __half g_wh[E_ * H_ * H_];   // pre-split weights [e][k][n]
__device__ __half g_wl[E_ * H_ * H_];
__device__ float  g_bias2[E_ * H_];
__device__ float  g_psum[1024][H_];
__device__ float  g_psq[1024][H_];
__device__ float  g_p2sum[16][H_];
__device__ float  g_p2sq[16][H_];
__device__ float  g_scale[H_];
__device__ float  g_shift[H_];
__device__ __align__(16) float g_rw[H_ * E_];
__device__ float  g_rc[E_];
__device__ int    g_act[B_];
__device__ int    g_cnt[E_];
__device__ int    g_off[E_];
__device__ int    g_pos[E_];
__device__ int    g_perm[B_];

__device__ __forceinline__ void mma_f16(float* c, const uint32_t* a, const uint32_t* b) {
    asm volatile(
        "mma.sync.aligned.m16n8k16.row.col.f32.f16.f16.f32 "
        "{%0,%1,%2,%3}, {%4,%5,%6,%7}, {%8,%9}, {%0,%1,%2,%3};"
        : "+f"(c[0]), "+f"(c[1]), "+f"(c[2]), "+f"(c[3])
        : "r"(a[0]), "r"(a[1]), "r"(a[2]), "r"(a[3]), "r"(b[0]), "r"(b[1]));
}
__device__ __forceinline__ void ldsm4(uint32_t* r, uint32_t saddr) {
    asm volatile("ldmatrix.sync.aligned.m8n8.x4.shared.b16 {%0,%1,%2,%3}, [%4];"
                 : "=r"(r[0]), "=r"(r[1]), "=r"(r[2]), "=r"(r[3]) : "r"(saddr));
}
__device__ __forceinline__ void ldsm4t(uint32_t* r, uint32_t saddr) {
    asm volatile("ldmatrix.sync.aligned.m8n8.x4.trans.shared.b16 {%0,%1,%2,%3}, [%4];"
                 : "=r"(r[0]), "=r"(r[1]), "=r"(r[2]), "=r"(r[3]) : "r"(saddr));
}
__device__ __forceinline__ void cpa16(uint32_t dst, const void* src) {
    asm volatile("cp.async.cg.shared.global [%0], [%1], 16;" :: "r"(dst), "l"(src));
}
__device__ __forceinline__ void cpa_commit() { asm volatile("cp.async.commit_group;" ::: "memory"); }
__device__ __forceinline__ void cpa_wait1()  { asm volatile("cp.async.wait_group 1;" ::: "memory"); }
__device__ __forceinline__ void cpa_wait0()  { asm volatile("cp.async.wait_group 0;" ::: "memory"); }
__device__ __forceinline__ uint32_t h2u(__half a, __half b) {
    const __half2 p = __halves2half2(a, b);
    return *(const uint32_t*)&p;
}

// SMEM per buffer: Ah[128x80B] Al[128x80B] Bh[32x272B] Bl[32x272B]
#define ROWB_    80                     // A row bytes (64 data + 16 pad)
#define BROWB_   272                    // B row bytes (256 data + 16 pad)
#define APART_B  (128 * ROWB_)          // 10240
#define BPART_B  (32 * BROWB_)          // 8704
#define BUFF_B   (2 * APART_B + 2 * BPART_B)   // 37888
#define SMEM_BYTES (2 * BUFF_B)                // 75776

// ===== 3xFP16-split mma.sync GEMM, pre-split operands, cp.async mainloop =====
// C = relu(A @ W + bias). A hi/lo [*,KK]; W hi/lo [e][k][n] (BN pre-folded).
// CTA tile 128x128, BK=32, 8 warps (2m x 4n), warp tile 64x32.
template<int KK, bool EXPERT, bool STATS, bool FP16OUT>
__global__ __launch_bounds__(256, 2) void mma_gemm(
    const __half* __restrict__ Agh, const __half* __restrict__ Agl,
    const __half* __restrict__ Wgh, const __half* __restrict__ Wgl,
    const float* __restrict__ biasAll,
    __half* __restrict__ Ch, __half* __restrict__ Cl,
    float* __restrict__ Cf, int ldw, int ldc)
{
    constexpr int NC = KK / 32;
    extern __shared__ __half smh[];

    const int tid  = threadIdx.x;
    const int wid  = tid >> 5;
    const int lane = tid & 31;
    const int gid  = lane >> 2;
    const int tig  = lane & 3;
    const int bm   = blockIdx.y * 128;
    const int bn0  = blockIdx.x * 128;
    const int slot = blockIdx.z * 128 + blockIdx.y;

    int cnt = B_, pbase = 0;
    const __half* Wph = Wgh;
    const __half* Wpl = Wgl;
    const float* bias = biasAll;
    if (EXPERT) {
        const int e = blockIdx.z;
        cnt = g_cnt[e];
        if (bm >= cnt) {
            if (STATS) {
                for (int i = tid; i < 128; i += 256) {
                    g_psum[slot][bn0 + i] = 0.f;
                    g_psq[slot][bn0 + i]  = 0.f;
                }
            }
            return;
        }
        pbase = g_off[e];
        Wph   = Wgh + (size_t)e * H_ * H_;
        Wpl   = Wgl + (size_t)e * H_ * H_;
        bias  = biasAll + (size_t)e * H_;
    }

    // ---- cp.async fill assignment ----
    // A: thread -> rows (crow, crow+64), 16B quarter cq
    const int crow = tid >> 2, cq = tid & 3;
    int gr0 = bm + crow, gr1 = bm + crow + 64;
    if (EXPERT) {
        gr0 = g_perm[pbase + (gr0 < cnt ? gr0 : cnt - 1)];
        gr1 = g_perm[pbase + (bm + crow + 64 < cnt ? bm + crow + 64 : cnt - 1)];
    }
    const __half* sa0h = Agh + (size_t)gr0 * KK + cq * 8;
    const __half* sa0l = Agl + (size_t)gr0 * KK + cq * 8;
    const __half* sa1h = Agh + (size_t)gr1 * KK + cq * 8;
    const __half* sa1l = Agl + (size_t)gr1 * KK + cq * 8;
    const uint32_t sbase = (uint32_t)__cvta_generic_to_shared(smh);
    const uint32_t da0 = (uint32_t)(crow * ROWB_ + cq * 16);
    const uint32_t da1 = da0 + 64 * ROWB_;
    // B: thread -> rows (brow, brow+16), 16B col c16
    const int brow = tid >> 4, c16 = tid & 15;
    const __half* sb0h = Wph + (size_t)brow * ldw + bn0 + c16 * 8;
    const __half* sb0l = Wpl + (size_t)brow * ldw + bn0 + c16 * 8;
    const __half* sb1h = sb0h + (size_t)16 * ldw;
    const __half* sb1l = sb0l + (size_t)16 * ldw;
    const uint32_t db0 = (uint32_t)(brow * BROWB_ + c16 * 16);
    const uint32_t db1 = db0 + 16 * BROWB_;

    auto fill = [&](int st, int c) {
        const uint32_t s = sbase + st * BUFF_B;
        const int ko = c * 32;                       // halfs along k (A)
        cpa16(s + da0,            sa0h + ko);
        cpa16(s + da1,            sa1h + ko);
        cpa16(s + APART_B + da0,  sa0l + ko);
        cpa16(s + APART_B + da1,  sa1l + ko);
        const size_t bko = (size_t)ko * ldw;         // k-rows (B)
        cpa16(s + 2 * APART_B + db0,           sb0h + bko);
        cpa16(s + 2 * APART_B + db1,           sb1h + bko);
        cpa16(s + 2 * APART_B + BPART_B + db0, sb0l + bko);
        cpa16(s + 2 * APART_B + BPART_B + db1, sb1l + bko);
    };

    // ---- accumulators & ldmatrix addressing (A: R10 layout; B: R15 trans) ----
    float acc[4][4][4] = {};
    const int mbase = (wid & 1) * 64;
    const int nbase = (wid >> 1) * 32;
    const uint32_t aLane = (uint32_t)((mbase + (lane & 15)) * ROWB_ + (lane >> 4) * 16);
    const uint32_t bLane = (uint32_t)((((lane >> 3) & 1) * 8 + (lane & 7)) * BROWB_
                                      + ((lane >> 3) >> 1) * 16 + nbase * 2);

    auto domma = [&](int buf) {
        const uint32_t aH = sbase + buf * BUFF_B + aLane;
        const uint32_t aL = aH + APART_B;
        const uint32_t bH = sbase + buf * BUFF_B + 2 * APART_B + bLane;
        const uint32_t bL = bH + BPART_B;
#pragma unroll
        for (int ks = 0; ks < 2; ks++) {
            uint32_t bh[2][4], bl[2][4];
#pragma unroll
            for (int ntp = 0; ntp < 2; ntp++) {
                const uint32_t off = (uint32_t)(ks * 16 * BROWB_ + ntp * 32);
                ldsm4t(bh[ntp], bH + off);
                ldsm4t(bl[ntp], bL + off);
            }
#pragma unroll
            for (int mt = 0; mt < 4; mt++) {
                uint32_t ah[4], al[4];
                const uint32_t off = (uint32_t)(mt * 16 * ROWB_ + ks * 32);
                ldsm4(ah, aH + off);
                ldsm4(al, aL + off);
#pragma unroll
                for (int nt = 0; nt < 4; nt++) {
                    const uint32_t* bhp = &bh[nt >> 1][(nt & 1) * 2];
                    const uint32_t* blp = &bl[nt >> 1][(nt & 1) * 2];
                    mma_f16(acc[mt][nt], ah, bhp);
                    mma_f16(acc[mt][nt], ah, blp);
                    mma_f16(acc[mt][nt], al, bhp);
                }
            }
        }
    };

    // ---- async pipeline ----
    fill(0, 0); cpa_commit();
    fill(1, 1); cpa_commit();
    for (int c = 0; c < NC; c++) {
        if (c + 2 < NC) cpa_wait1(); else cpa_wait0();
        __syncthreads();
        domma(c & 1);
        __syncthreads();
        if (c + 2 < NC) { fill(c & 1, c + 2); cpa_commit(); }
    }

    // ---- epilogue: bias + relu (+ fused stats, + hi/lo split out) ----
    float cs[4][2], cq2[4][2];
    if (STATS) {
#pragma unroll
        for (int nt = 0; nt < 4; nt++) {
            cs[nt][0] = cs[nt][1] = 0.f;
            cq2[nt][0] = cq2[nt][1] = 0.f;
        }
    }
#pragma unroll
    for (int mt = 0; mt < 4; mt++) {
#pragma unroll
        for (int half = 0; half < 2; half++) {
            const int lrow = mbase + mt * 16 + gid + half * 8;
            bool valid = true;
            int orow = bm + lrow;
            if (EXPERT) {
                valid = (bm + lrow) < cnt;
                orow  = valid ? g_perm[pbase + bm + lrow] : 0;
            }
            if (!valid) continue;
#pragma unroll
            for (int nt = 0; nt < 4; nt++) {
                const int n = nbase + nt * 8 + tig * 2;
                const float2 bv = *(const float2*)(bias + bn0 + n);
                const float ox = fmaxf(acc[mt][nt][half * 2 + 0] + bv.x, 0.f);
                const float oy = fmaxf(acc[mt][nt][half * 2 + 1] + bv.y, 0.f);
                if (STATS) {
                    cs[nt][0] += ox; cq2[nt][0] += ox * ox;
                    cs[nt][1] += oy; cq2[nt][1] += oy * oy;
                }
                if (FP16OUT) {
                    const __half hx = __float2half_rn(ox);
                    const __half hy = __float2half_rn(oy);
                    const __half lx = __float2half_rn(ox - __half2float(hx));
                    const __half ly = __float2half_rn(oy - __half2float(hy));
                    *(uint32_t*)(Ch + (size_t)orow * ldc + bn0 + n) = h2u(hx, hy);
                    *(uint32_t*)(Cl + (size_t)orow * ldc + bn0 + n) = h2u(lx, ly);
                } else {
                    float2 o; o.x = ox; o.y = oy;
                    *(float2*)(Cf + (size_t)orow * ldc + bn0 + n) = o;
                }
            }
        }
    }

    if (STATS) {
        __shared__ float s_cs[128], s_cq[128];
        __syncthreads();
        for (int i = tid; i < 128; i += 256) { s_cs[i] = 0.f; s_cq[i] = 0.f; }
        __syncthreads();
#pragma unroll
        for (int nt = 0; nt < 4; nt++) {
#pragma unroll
            for (int cc = 0; cc < 2; cc++) {
                float v = cs[nt][cc], w = cq2[nt][cc];
#pragma unroll
                for (int mk = 4; mk <= 16; mk <<= 1) {
                    v += __shfl_xor_sync(0xffffffffu, v, mk);
                    w += __shfl_xor_sync(0xffffffffu, w, mk);
                }
                if (gid == 0) {
                    const int col = nbase + nt * 8 + tig * 2 + cc;
                    atomicAdd(&s_cs[col], v);    // exactly 2 adds/col: deterministic
                    atomicAdd(&s_cq[col], w);
                }
            }
        }
        __syncthreads();
        for (int i = tid; i < 128; i += 256) {
            g_psum[slot][bn0 + i] = s_cs[i];
            g_psq[slot][bn0 + i]  = s_cq[i];
        }
    }
}

// ---------------- split x into hi/lo fp16 ----------------
__global__ void split_x(const float* __restrict__ x,
                        __half* __restrict__ xh, __half* __restrict__ xl)
{
    const int idx = (blockIdx.x * 256 + threadIdx.x) * 4;
    const float4 v = *(const float4*)(x + idx);
    const float vv[4] = { v.x, v.y, v.z, v.w };
    __half h[4], l[4];
#pragma unroll
    for (int q = 0; q < 4; q++) {
        h[q] = __float2half_rn(vv[q]);
        l[q] = __float2half_rn(vv[q] - __half2float(h[q]));
    }
    uint2 uh, ul;
    uh.x = h2u(h[0], h[1]); uh.y = h2u(h[2], h[3]);
    ul.x = h2u(l[0], l[1]); ul.y = h2u(l[2], l[3]);
    *(uint2*)(xh + idx) = uh;
    *(uint2*)(xl + idx) = ul;
}

// ------- wsplit: W[e][k][n] fp32 -> hi/lo fp16, row-scaled by s_k (optional) -
// grid (N/128, K/8, E), block 256.
__global__ void wsplit(const float* __restrict__ W, const float* __restrict__ s,
                       __half* __restrict__ Wh, __half* __restrict__ Wl,
                       int N, int K)
{
    const int e = blockIdx.z;
    const int k = blockIdx.y * 8 + (threadIdx.x >> 5);
    const int n = blockIdx.x * 128 + (threadIdx.x & 31) * 4;
    const size_t off = (size_t)e * K * N + (size_t)k * N + n;
    float4 w = *(const float4*)(W + off);
    const float sc = s ? s[k] : 1.f;
    w.x *= sc; w.y *= sc; w.z *= sc; w.w *= sc;
    const float vv[4] = { w.x, w.y, w.z, w.w };
    __half h[4], l[4];
#pragma unroll
    for (int q = 0; q < 4; q++) {
        h[q] = __float2half_rn(vv[q]);
        l[q] = __float2half_rn(vv[q] - __half2float(h[q]));
    }
    uint2 uh, ul;
    uh.x = h2u(h[0], h[1]); uh.y = h2u(h[2], h[3]);
    ul.x = h2u(l[0], l[1]); ul.y = h2u(l[2], l[3]);
    *(uint2*)(Wh + off) = uh;
    *(uint2*)(Wl + off) = ul;
}

// ------- wbias: bias_out[e][n] = bias_in[e][n] + sum_k shift_k * W[e][k][n] --
// grid (N/128, E), block 256. Deterministic (fixed k order, fixed warp order).
__global__ void wbias(const float* __restrict__ W, const float* __restrict__ bin,
                      float* __restrict__ bout, int N, int K)
{
    __shared__ float red[8][128];
    const int e = blockIdx.y;
    const int w = threadIdx.x >> 5;
    const int lane = threadIdx.x & 31;
    const int n = blockIdx.x * 128 + lane * 4;
    const float* We_ = W + (size_t)e * K * N;
    float4 acc = make_float4(0.f, 0.f, 0.f, 0.f);
    for (int k = w; k < K; k += 8) {
        const float t = g_shift[k];
        const float4 wv = *(const float4*)(We_ + (size_t)k * N + n);
        acc.x += t * wv.x; acc.y += t * wv.y;
        acc.z += t * wv.z; acc.w += t * wv.w;
    }
    *(float4*)&red[w][lane * 4] = acc;
    __syncthreads();
    if (w == 0) {
        float4 s = make_float4(0.f, 0.f, 0.f, 0.f);
#pragma unroll
        for (int ww = 0; ww < 8; ww++) {
            const float4 r = *(const float4*)&red[ww][lane * 4];
            s.x += r.x; s.y += r.y; s.z += r.z; s.w += r.w;
        }
        const float4 b4 = *(const float4*)(bin + (size_t)e * N + n);
        float4 o;
        o.x = b4.x + s.x; o.y = b4.y + s.y; o.z = b4.z + s.z; o.w = b4.w + s.w;
        *(float4*)(bout + (size_t)e * N + n) = o;
    }
}

// ---------------- stage-2 partial reduction: npart slots -> 16 ---------------
__global__ void bn_reduce(int npart)
{
    __shared__ float ss[8][33], sq[8][33];
    const int tx = threadIdx.x, ty = threadIdx.y;
    const int col = blockIdx.x * 32 + tx;
    const int per = npart >> 4;
    const int base = blockIdx.y * per;
    float s = 0.f, q = 0.f;
    for (int p = ty; p < per; p += 8) {
        s += g_psum[base + p][col];
        q += g_psq[base + p][col];
    }
    ss[ty][tx] = s; sq[ty][tx] = q;
    __syncthreads();
    if (ty == 0) {
#pragma unroll
        for (int y = 1; y < 8; y++) { s += ss[y][tx]; q += sq[y][tx]; }
        g_p2sum[blockIdx.y][col] = s;
        g_p2sq[blockIdx.y][col]  = q;
    }
}

// ------- finalize + prep_route fused: scale/shift, rw/rc, zero counters ------
__global__ void finalize_route(const float* __restrict__ gamma,
                               const float* __restrict__ beta,
                               const float* __restrict__ W,    // [H,E]
                               const float* __restrict__ b)    // [E]
{
    __shared__ float sS[H_], sT[H_];
    __shared__ float red[8][E_];
    const int tid  = threadIdx.x;
    const int lane = tid & 31, warp = tid >> 5;
    for (int c = tid; c < H_; c += 256) {
        float s = 0.f, q = 0.f;
#pragma unroll
        for (int p = 0; p < 16; p++) { s += g_p2sum[p][c]; q += g_p2sq[p][c]; }
        const float m   = s * (1.f / B_);
        const float var = q * (1.f / B_) - m * m;
        const float sc  = gamma[c] / sqrtf(var + EPS_);
        const float sh  = beta[c] - m * sc;
        g_scale[c] = sc; g_shift[c] = sh;
        sS[c] = sc; sT[c] = sh;
    }
    __syncthreads();
    float tacc[E_] = {};
    for (int c = tid; c < H_; c += 256) {
        const float s = sS[c], t = sT[c];
        const float4 w0 = *(const float4*)(W + c * E_);
        const float4 w1 = *(const float4*)(W + c * E_ + 4);
        float4 o0, o1;
        o0.x = s * w0.x; o0.y = s * w0.y; o0.z = s * w0.z; o0.w = s * w0.w;
        o1.x = s * w1.x; o1.y = s * w1.y; o1.z = s * w1.z; o1.w = s * w1.w;
        *(float4*)(g_rw + c * E_)     = o0;
        *(float4*)(g_rw + c * E_ + 4) = o1;
        tacc[0] += t * w0.x; tacc[1] += t * w0.y;
        tacc[2] += t * w0.z; tacc[3] += t * w0.w;
        tacc[4] += t * w1.x; tacc[5] += t * w1.y;
        tacc[6] += t * w1.z; tacc[7] += t * w1.w;
    }
#pragma unroll
    for (int e = 0; e < E_; e++)
#pragma unroll
        for (int off = 16; off; off >>= 1)
            tacc[e] += __shfl_xor_sync(0xffffffffu, tacc[e], off);
    if (lane == 0)
#pragma unroll
        for (int e = 0; e < E_; e++) red[warp][e] = tacc[e];
    __syncthreads();
    if (tid < E_) {
        float s = 0.f;
#pragma unroll
        for (int w = 0; w < 8; w++) s += red[w][tid];
        g_rc[tid] = s + b[tid];
        g_cnt[tid] = 0;
    }
}

// ---------------- routing: 4 rows/warp, swizzled smem weights, hi/lo A -------
#define SWZ_(o) ((o) ^ (((o) >> 3) & 0x70))

__global__ __launch_bounds__(256)
void mlnn_routing(const __half* __restrict__ hh, const __half* __restrict__ hl)
{
    __shared__ __align__(16) char Wt[H_ * E_ * 4];   // 16 KB, swizzled
    __shared__ float rc[E_];
    const int tid = threadIdx.x;
    {
        const float4* src = (const float4*)g_rw;
        for (int i = tid; i < H_ * E_ / 4; i += 256) {
            const uint32_t o = (uint32_t)(i * 16);
            *(float4*)(Wt + SWZ_(o)) = src[i];
        }
        if (tid < E_) rc[tid] = g_rc[tid];
    }
    __syncthreads();
    const int warp = tid >> 5, lane = tid & 31;
    const int row0 = blockIdx.x * 32 + warp * 4;
    const uint2* rh[4]; const uint2* rl[4];
#pragma unroll
    for (int r = 0; r < 4; r++) {
        rh[r] = (const uint2*)(hh + (size_t)(row0 + r) * H_);
        rl[r] = (const uint2*)(hl + (size_t)(row0 + r) * H_);
    }

    float acc[4][E_];
#pragma unroll
    for (int r = 0; r < 4; r++)
#pragma unroll
        for (int e = 0; e < E_; e++) acc[r][e] = 0.f;

#pragma unroll
    for (int i = 0; i < H_ / 128; i++) {
        const int k4 = i * 32 + lane;                // 4 halfs at index k4
        float va[4][4];
#pragma unroll
        for (int r = 0; r < 4; r++) {
            const uint2 uh = rh[r][k4];
            const uint2 ul = rl[r][k4];
            const float2 f0 = __half22float2(*(const __half2*)&uh.x);
            const float2 f1 = __half22float2(*(const __half2*)&uh.y);
            const float2 g0 = __half22float2(*(const __half2*)&ul.x);
            const float2 g1 = __half22float2(*(const __half2*)&ul.y);
            va[r][0] = f0.x + g0.x; va[r][1] = f0.y + g0.y;
            va[r][2] = f1.x + g1.x; va[r][3] = f1.y + g1.y;
        }
        const uint32_t ob = (uint32_t)(i * 4096 + lane * 128);
#pragma unroll
        for (int j = 0; j < 4; j++) {
            float w[8];
            const uint32_t o = ob + j * 32;
            *(float4*)(w)     = *(const float4*)(Wt + SWZ_(o));
            *(float4*)(w + 4) = *(const float4*)(Wt + SWZ_(o + 16));
#pragma unroll
            for (int e = 0; e < E_; e++)
#pragma unroll
                for (int r = 0; r < 4; r++)
                    acc[r][e] = fmaf(va[r][j], w[e], acc[r][e]);
        }
    }

#pragma unroll
    for (int r = 0; r < 4; r++)
#pragma unroll
        for (int e = 0; e < E_; e++)
#pragma unroll
            for (int off = 16; off; off >>= 1)
                acc[r][e] += __shfl_xor_sync(0xffffffffu, acc[r][e], off);

    if (lane == 0) {
#pragma unroll
        for (int r = 0; r < 4; r++) {
            float best = acc[r][0] + rc[0];
            int bi = 0;
#pragma unroll
            for (int e = 1; e < E_; e++) {
                const float v = acc[r][e] + rc[e];
                if (v > best) { best = v; bi = e; }   // strict > == jnp first-max
            }
            g_act[row0 + r] = bi;
            atomicAdd(&g_cnt[bi], 1);
        }
    }
}

__global__ void mlnn_scan()
{
    if (threadIdx.x == 0) {
        int s = 0;
#pragma unroll
        for (int e = 0; e < E_; e++) { g_off[e] = s; g_pos[e] = s; s += g_cnt[e]; }
    }
}

__global__ void mlnn_scatter()
{
    const int r = blockIdx.x * 256 + threadIdx.x;
    const int a = g_act[r];
    const int p = atomicAdd(&g_pos[a], 1);
    g_perm[p] = r;
}

// ---------------- launch ----------------
extern "C" void kernel_launch(void* const* d_in, const int* in_sizes, int n_in,
                              void* d_out, int out_size)
{
    const float* x     = (const float*)d_in[0];
    const float* dqn_W = (const float*)d_in[1];
    const float* dqn_b = (const float*)d_in[2];
    const float* Ws    = (const float*)d_in[3];
    const float* bs    = (const float*)d_in[4];
    const float* g0    = (const float*)d_in[5];
    const float* b0    = (const float*)d_in[6];
    const float* We    = (const float*)d_in[7];
    const float* be    = (const float*)d_in[8];
    const float* gmid  = (const float*)d_in[9];
    const float* bmid  = (const float*)d_in[10];
    const float* Wend  = (const float*)d_in[11];
    const float* bend  = (const float*)d_in[12];
    float* out = (float*)d_out;

    __half *xh, *xl, *ah, *al, *bh, *bl, *wh, *wl;
    float *scl, *bias2;
    cudaGetSymbolAddress((void**)&xh, g_xh);
    cudaGetSymbolAddress((void**)&xl, g_xl);
    cudaGetSymbolAddress((void**)&ah, g_ah);
    cudaGetSymbolAddress((void**)&al, g_al);
    cudaGetSymbolAddress((void**)&bh, g_bh);
    cudaGetSymbolAddress((void**)&bl, g_bl);
    cudaGetSymbolAddress((void**)&wh, g_wh);
    cudaGetSymbolAddress((void**)&wl, g_wl);
    cudaGetSymbolAddress((void**)&scl,   g_scale);
    cudaGetSymbolAddress((void**)&bias2, g_bias2);

    cudaFuncSetAttribute(mma_gemm<1024, false, true, true>,
                         cudaFuncAttributeMaxDynamicSharedMemorySize, SMEM_BYTES);
    cudaFuncSetAttribute(mma_gemm<512, true, true, true>,
                         cudaFuncAttributeMaxDynamicSharedMemorySize, SMEM_BYTES);
    cudaFuncSetAttribute(mma_gemm<512, false, false, false>,
                         cudaFuncAttributeMaxDynamicSharedMemorySize, SMEM_BYTES);

    // ---- input + start-weight prep ----
    split_x<<<B_ * DIN_ / 1024, 256>>>(x, xh, xl);
    wsplit<<<dim3(H_ / 128, DIN_ / 8, 1), 256>>>(Ws, nullptr, wh, wl, H_, DIN_);

    // ---- start layer ----
    mma_gemm<1024, false, true, true><<<dim3(H_ / 128, B_ / 128), 256, SMEM_BYTES>>>(
        xh, xl, wh, wl, bs, ah, al, nullptr, H_, H_);
    bn_reduce<<<dim3(H_ / 32, 16), dim3(32, 8)>>>(128);
    finalize_route<<<1, 256>>>(g0, b0, dqn_W, dqn_b);

    const __half* curh = ah; const __half* curl = al;
    __half* outs[2][2] = { { bh, bl }, { xh, xl } };   // xh/xl reused for mid-1
    for (int l = 0; l < NMID_; l++) {
        mlnn_routing<<<B_ / 32, 256>>>(curh, curl);
        mlnn_scan<<<1, 1>>>();
        mlnn_scatter<<<B_ / 256, 256>>>();
        const float* WeL = We + (size_t)l * E_ * H_ * H_;
        wsplit<<<dim3(H_ / 128, H_ / 8, E_), 256>>>(WeL, scl, wh, wl, H_, H_);
        wbias<<<dim3(H_ / 128, E_), 256>>>(WeL, be + (size_t)l * E_ * H_, bias2, H_, H_);
        mma_gemm<512, true, true, true><<<dim3(H_ / 128, B_ / 128, E_), 256, SMEM_BYTES>>>(
            curh, curl, wh, wl, bias2, outs[l][0], outs[l][1], nullptr, H_, H_);
        bn_reduce<<<dim3(H_ / 32, 16), dim3(32, 8)>>>(1024);
        finalize_route<<<1, 256>>>(gmid + (size_t)l * H_, bmid + (size_t)l * H_,
                                   dqn_W, dqn_b);
        curh = outs[l][0]; curl = outs[l][1];
    }

    // ---- end layer ----
    wsplit<<<dim3(DOUT_ / 128, H_ / 8, 1), 256>>>(Wend, scl, wh, wl, DOUT_, H_);
    wbias<<<dim3(DOUT_ / 128, 1), 256>>>(Wend, bend, bias2, DOUT_, H_);
    mma_gemm<512, false, false, false><<<dim3(DOUT_ / 128, B_ / 128), 256, SMEM_BYTES>>>(
        curh, curl, wh, wl, bias2, nullptr, nullptr, out, DOUT_, DOUT_);
}